// round 4
// baseline (speedup 1.0000x reference)
#include <cuda_runtime.h>
#include <cuda_bf16.h>

// TSAdaptivePatcher: PATCH_SIZE == STRIDE == 16 -> non-overlapping windows.
//   x:    [B=64, C=64, S=8192] f32
//   mask: [B=64, S=8192] i32 (0/1)
// Outputs (concatenated in d_out, f32):
//   patches      [B, 512, C*16=1024]  : patches[b,p,c*16+j] = x[b,c,p*16+j]
//   padding_mask [B, 512]             : (sum_{j<16} mask[b,p*16+j] >= 8) ? 1 : 0
//
// Pure 64B-granularity permutation -> HBM-bound streaming copy.
// float4 per thread; __ldcs/__stcs streaming hints (no reuse; x > L2).

static constexpr int B = 64;
static constexpr int C = 64;
static constexpr int S = 8192;
static constexpr int NPATCH = 512;                 // 1 + (S-16)/16
static constexpr long PATCH_ELEMS = (long)B * NPATCH * C * 16;   // 33,554,432
static constexpr int N_COPY_V4 = (int)(PATCH_ELEMS / 4);         // 8,388,608 = 2^23
static constexpr int N_MASK = B * NPATCH;                        // 32,768

__global__ void __launch_bounds__(256) patch_copy_kernel(
    const float4* __restrict__ in, float4* __restrict__ out)
{
    int i = blockIdx.x * 256 + threadIdx.x;   // output-linear float4 index
    // out layout: [b (6b)][p (9b)][c (6b)][jv (2b)]
    int jv = i & 3;
    int c  = (i >> 2) & 63;
    int p  = (i >> 8) & 511;
    int b  = i >> 17;
    // in float4 index: ((b*C + c) * S + p*16)/4 + jv
    int src = (((b << 6) + c) << 11) + (p << 2) + jv;
    float4 v = __ldcs(in + src);
    __stcs(out + i, v);
}

__global__ void __launch_bounds__(256) patch_mask_kernel(
    const int4* __restrict__ mask, float* __restrict__ out)
{
    int i = blockIdx.x * 256 + threadIdx.x;   // i = b*512 + p, 0..32767
    const int4* mp = mask + (i << 2);         // 16 ints per patch, contiguous
    int s = 0;
#pragma unroll
    for (int k = 0; k < 4; k++) {
        int4 v = __ldcs(mp + k);
        s += v.x + v.y + v.z + v.w;
    }
    // valid_ratio >= 0.5  <=>  sum >= 8 (exact integer compare)
    out[i] = (s >= 8) ? 1.0f : 0.0f;
}

extern "C" void kernel_launch(void* const* d_in, const int* in_sizes, int n_in,
                              void* d_out, int out_size)
{
    (void)in_sizes; (void)n_in; (void)out_size;
    const float4* x    = (const float4*)d_in[0];
    const int4*   mask = (const int4*)d_in[1];
    float* out = (float*)d_out;

    patch_copy_kernel<<<N_COPY_V4 / 256, 256>>>(x, (float4*)out);
    patch_mask_kernel<<<N_MASK / 256, 256>>>(mask, out + PATCH_ELEMS);
}

// round 5
// speedup vs baseline: 1.1670x; 1.1670x over previous
#include <cuda_runtime.h>
#include <cuda_bf16.h>

// TSAdaptivePatcher: PATCH_SIZE == STRIDE == 16 -> non-overlapping windows.
//   x:    [B=64, C=64, S=8192] f32
//   mask: [B=64, S=8192] i32 (0/1)
// Outputs (concatenated in d_out, f32):
//   patches      [B, 512, 1024] : patches[b,p,c*16+j] = x[b,c,p*16+j]
//   padding_mask [B, 512]       : (sum_{j<16} mask[b,p*16+j] >= 8) ? 1 : 0
//
// Single fused kernel:
//  - blocks [0, MASK_BLOCKS): mask reduction (tiny, hides under the copy)
//  - blocks [MASK_BLOCKS, ..): streaming 64B-granule permutation, ILP=4
//    independent float4s per thread (MLP=4), fully coalesced on both sides,
//    __ldcs/__stcs (zero reuse; working set >> L2).

static constexpr int B = 64;
static constexpr int C = 64;
static constexpr int S = 8192;
static constexpr int NPATCH = 512;
static constexpr long PATCH_ELEMS = (long)B * NPATCH * C * 16;   // 33,554,432
static constexpr int N_COPY_V4 = (int)(PATCH_ELEMS / 4);         // 8,388,608 = 2^23
static constexpr int N_MASK = B * NPATCH;                        // 32,768

static constexpr int TPB = 256;
static constexpr int ILP = 4;
static constexpr int COPY_BLOCKS = N_COPY_V4 / (TPB * ILP);      // 8192
static constexpr int MASK_BLOCKS = N_MASK / TPB;                 // 128

__global__ void __launch_bounds__(TPB) fused_patcher_kernel(
    const float4* __restrict__ x,
    const int4*   __restrict__ mask,
    float4* __restrict__ out_patches,
    float*  __restrict__ out_mask)
{
    int bid = blockIdx.x;

    if (bid < MASK_BLOCKS) {
        // ---- mask reduction: i = b*512 + p ----
        int i = bid * TPB + threadIdx.x;
        const int4* mp = mask + (i << 2);        // 16 contiguous ints per patch
        int s = 0;
#pragma unroll
        for (int k = 0; k < 4; k++) {
            int4 v = __ldcs(mp + k);
            s += v.x + v.y + v.z + v.w;
        }
        // valid_ratio >= 0.5  <=>  integer sum >= 8 (exact)
        out_mask[i] = (s >= 8) ? 1.0f : 0.0f;
        return;
    }

    // ---- streaming permutation, output-linear, ILP=4 ----
    int cb = bid - MASK_BLOCKS;
    int base = cb * (TPB * ILP) + threadIdx.x;

    float4 v[ILP];
    int dst[ILP];
#pragma unroll
    for (int k = 0; k < ILP; k++) {
        int i = base + k * TPB;                  // output-linear float4 index
        // out layout bits: [b:6][p:9][c:6][jv:2]
        int jv = i & 3;
        int c  = (i >> 2) & 63;
        int p  = (i >> 8) & 511;
        int b  = i >> 17;
        // src float4 index: ((b*64 + c) * 8192 + p*16)/4 + jv
        int src = (((b << 6) + c) << 11) + (p << 2) + jv;
        dst[k] = i;
        v[k] = __ldcs(x + src);                  // 4 independent loads, MLP=4
    }
#pragma unroll
    for (int k = 0; k < ILP; k++)
        __stcs(out_patches + dst[k], v[k]);
}

extern "C" void kernel_launch(void* const* d_in, const int* in_sizes, int n_in,
                              void* d_out, int out_size)
{
    (void)in_sizes; (void)n_in; (void)out_size;
    const float4* x    = (const float4*)d_in[0];
    const int4*   mask = (const int4*)d_in[1];
    float* out = (float*)d_out;

    fused_patcher_kernel<<<MASK_BLOCKS + COPY_BLOCKS, TPB>>>(
        x, mask, (float4*)out, out + PATCH_ELEMS);
}

// round 6
// speedup vs baseline: 1.1841x; 1.0146x over previous
#include <cuda_runtime.h>
#include <cuda_bf16.h>

// TSAdaptivePatcher: PATCH_SIZE == STRIDE == 16 -> non-overlapping windows.
//   x:    [B=64, C=64, S=8192] f32
//   mask: [B=64, S=8192] i32 (0/1)
// Outputs (concatenated in d_out, f32):
//   patches      [B, 512, 1024] : patches[b,p,c*16+j] = x[b,c,p*16+j]
//   padding_mask [B, 512]       : (sum_{j<16} mask[b,p*16+j] >= 8) ? 1 : 0
//
// Fused single launch:
//  - blocks [0, MASK_BLOCKS): mask reduction (hides under the copy)
//  - copy blocks: ILP=8 independent float4s per thread, k-stride = TPB.
//    Output-linear i stepping by 256 increments the p-field -> each thread's
//    8 source chunks are CONTIGUOUS (512B/thread read runs), warp reads
//    8 c-rows x 512B. MLP=8 covers the 577cyc DRAM latency at ~50% occ.

static constexpr int B = 64;
static constexpr int C = 64;
static constexpr int S = 8192;
static constexpr int NPATCH = 512;
static constexpr long PATCH_ELEMS = (long)B * NPATCH * C * 16;   // 33,554,432
static constexpr int N_COPY_V4 = (int)(PATCH_ELEMS / 4);         // 8,388,608 = 2^23
static constexpr int N_MASK = B * NPATCH;                        // 32,768

static constexpr int TPB = 256;
static constexpr int ILP = 8;
static constexpr int COPY_BLOCKS = N_COPY_V4 / (TPB * ILP);      // 4096
static constexpr int MASK_BLOCKS = N_MASK / TPB;                 // 128

__global__ void __launch_bounds__(TPB) fused_patcher_kernel(
    const float4* __restrict__ x,
    const int4*   __restrict__ mask,
    float4* __restrict__ out_patches,
    float*  __restrict__ out_mask)
{
    int bid = blockIdx.x;

    if (bid < MASK_BLOCKS) {
        // ---- mask reduction: i = b*512 + p ----
        int i = bid * TPB + threadIdx.x;
        const int4* mp = mask + (i << 2);        // 16 contiguous ints per patch
        int s = 0;
#pragma unroll
        for (int k = 0; k < 4; k++) {
            int4 v = __ldcs(mp + k);
            s += v.x + v.y + v.z + v.w;
        }
        // valid_ratio >= 0.5  <=>  integer sum >= 8 (exact)
        out_mask[i] = (s >= 8) ? 1.0f : 0.0f;
        return;
    }

    // ---- streaming permutation, output-linear, ILP=8 ----
    int cb = bid - MASK_BLOCKS;
    int base = cb * (TPB * ILP) + threadIdx.x;

    // Decode source once; i += TPB(=256) increments the p field (bit 8),
    // so src advances by 4 float4s (64B) per k: contiguous per-thread reads.
    {
        int i0 = base;
        int jv = i0 & 3;
        int c  = (i0 >> 2) & 63;
        int p  = (i0 >> 8) & 511;
        int b  = i0 >> 17;
        int src0 = (((b << 6) + c) << 11) + (p << 2) + jv;

        float4 v[ILP];
#pragma unroll
        for (int k = 0; k < ILP; k++)
            v[k] = __ldcs(x + src0 + k * 4);     // 8 independent, contiguous 64B
#pragma unroll
        for (int k = 0; k < ILP; k++)
            __stcs(out_patches + base + k * TPB, v[k]);
    }
}

extern "C" void kernel_launch(void* const* d_in, const int* in_sizes, int n_in,
                              void* d_out, int out_size)
{
    (void)in_sizes; (void)n_in; (void)out_size;
    const float4* x    = (const float4*)d_in[0];
    const int4*   mask = (const int4*)d_in[1];
    float* out = (float*)d_out;

    fused_patcher_kernel<<<MASK_BLOCKS + COPY_BLOCKS, TPB>>>(
        x, mask, (float4*)out, out + PATCH_ELEMS);
}